// round 14
// baseline (speedup 1.0000x reference)
#include <cuda_runtime.h>
#include <cstdint>

#define BATCH 4096
#define IN_F 128
#define OUT_F 128
#define NW (IN_F * OUT_F)
#define NCH 36               // 36 x-chunks (9e x 4 i-groups); bias via epilogue

// B operand in EXACT mma-fragment order (tf32-rounded), 36 chunks:
// d_Btf[((c*16 + nb)*2 + p)*128 + lane*4 + e2]
__device__ float d_Btf[NCH * 16 * 2 * 128];
// Bias generator WB[e][o] (fp32)
__device__ float d_WB[9 * 128];

// ---------------------------------------------------------------------------
// Helpers (baseline PTX only — toolchain compiles via compute_103, no tcgen05)
// ---------------------------------------------------------------------------
__device__ __forceinline__ float tf32r(float x) {
    uint32_t r;
    asm("cvt.rn.tf32.f32 %0, %1;" : "=r"(r) : "f"(x));
    return __uint_as_float(r);
}
__device__ __forceinline__ void mma_tf32(float& d0, float& d1, float& d2, float& d3,
                                         uint32_t a0, uint32_t a1, uint32_t a2, uint32_t a3,
                                         uint32_t b0, uint32_t b1) {
    asm volatile(
        "mma.sync.aligned.m16n8k8.row.col.f32.tf32.tf32.f32 "
        "{%0,%1,%2,%3}, {%4,%5,%6,%7}, {%8,%9}, {%0,%1,%2,%3};"
        : "+f"(d0), "+f"(d1), "+f"(d2), "+f"(d3)
        : "r"(a0), "r"(a1), "r"(a2), "r"(a3), "r"(b0), "r"(b1));
}

// ---------------------------------------------------------------------------
// Prep: build d_Btf (chunks 0..35, k always < 1152) and d_WB.
// Block = (c, nb); thread -> (p, lane, e2). Coalesced write.
// ---------------------------------------------------------------------------
__global__ __launch_bounds__(256) void b_kernel(const float* __restrict__ gen_W,
                                                const float* __restrict__ gen_b) {
    const int c  = blockIdx.x >> 4;
    const int nb = blockIdx.x & 15;
    const int tid = threadIdx.x;
    const int p  = tid >> 7;
    const int l  = (tid >> 2) & 31;
    const int e2 = tid & 3;
    const int g = l >> 2, q = l & 3;
    const int o = nb * 8 + g;
    const int k = c * 32 + 16 * p + 8 * (e2 >> 1) + 4 * (e2 & 1) + q;
    const int e = k >> 7, i = k & 127, p8 = o * 128 + i;
    const float v = (e < 8) ? gen_W[p8 * 8 + e] : gen_b[p8];
    d_Btf[blockIdx.x * 256 + tid] = tf32r(v);

    // WB fill from first 5 blocks (9*128 = 1152 = 4.5 blocks of 256)
    const int j = blockIdx.x * 256 + tid;
    if (j < 9 * 128) {
        const int eb = j >> 7, ob = j & 127;
        d_WB[j] = (eb < 8) ? gen_W[(NW + ob) * 8 + eb] : gen_b[NW + ob];
    }
}

// ---------------------------------------------------------------------------
// Fused GEMM: CTA 256 thr, tile M=64 x N=64, grid 128 = (m-tile) x (n-half).
// Warp tile M32 x N16: wr=wid&1 (m-half of CTA), wc=wid>>1 (16 cols).
// x-tile stored FRAGMENT-MAJOR: xt[row][ii][q'][ki] (f4 pitch 36/row) ->
// A-frags are 8x LDS.128/chunk, conflict-free (row stride 144 fl = 16 mod 32).
// B: 3-buffer register ring (48 regs), prefetch distance 2.
// Bias: fp32 FFMA epilogue from smem WB. No mainloop barriers.
// ---------------------------------------------------------------------------
__global__ __launch_bounds__(256, 1) void gemm_kernel(
    const float* __restrict__ x,
    const float* __restrict__ features,
    const float* __restrict__ fc0_W, const float* __restrict__ fc0_b,
    const float* __restrict__ a0p,
    const float* __restrict__ fc1_W, const float* __restrict__ fc1_b,
    const float* __restrict__ a1p,
    float* __restrict__ out)
{
    __shared__ __align__(16) float4 xt[64 * 36];   // 36.9 KB fragment-major x (tf32)
    __shared__ float cs[64 * 12];                  // coeffs, pitch 12
    __shared__ float wb[9 * 128];                  // bias generator

    const int tid = threadIdx.x, wid = tid >> 5, lid = tid & 31;
    const int mt = blockIdx.x >> 1, nh = blockIdx.x & 1;
    const int b0row = mt * 64;
    const int wr = wid & 1, wc = wid >> 1;         // 2 m-warps x 4 n-warps
    const int m0 = wr * 32;
    const int nbb = nh * 8 + wc * 2;               // n-block base (units of 8 cols), ni 0..1
    const int g = lid >> 2, q = lid & 3;

    // ---- B: 4 x LDG.128 per chunk, ring of 3, prefetch distance 2 ----
    const float4* bp = (const float4*)d_Btf;       // f4: ((c*16+nb)*2+p)*32 + lane
    float4 br[3][4];                               // [buf][ni*2+p]
    #define LOADB(buf, c)                                                     \
        _Pragma("unroll")                                                     \
        for (int ni = 0; ni < 2; ni++) {                                      \
            _Pragma("unroll")                                                 \
            for (int p = 0; p < 2; p++)                                       \
                br[buf][ni * 2 + p] =                                         \
                    __ldg(bp + (((c) * 16 + nbb + ni) * 2 + p) * 32 + lid);   \
        }
    LOADB(0, 0)
    LOADB(1, 1)

    // ---- x tile, fragment-major, tf32-rounded at fill ----
    // slot s: r=s>>5, w=s&31 -> ii=w>>3, q'=w&7 ; float4 = x[r][32ii+q'+8*ki]
    #pragma unroll
    for (int j = 0; j < 8; j++) {
        const int s = tid + 256 * j;
        const int r = s >> 5, w = s & 31;
        const float* xr = x + (size_t)(b0row + r) * IN_F + (w >> 3) * 32 + (w & 7);
        float4 v;
        v.x = tf32r(xr[0]);  v.y = tf32r(xr[8]);
        v.z = tf32r(xr[16]); v.w = tf32r(xr[24]);
        xt[r * 36 + w] = v;
    }

    // ---- WB -> smem ----
    #pragma unroll
    for (int j = tid; j < 9 * 128; j += 256) wb[j] = d_WB[j];

    // ---- tiny MLP: threads 0-63, one sample each -> cs[row][e] (fp32) ----
    if (tid < 64) {
        const int b = b0row + tid;
        const float a0 = a0p[0], a1 = a1p[0];
        float h0[16];
        #pragma unroll
        for (int j = 0; j < 16; j++) {
            float s = fc0_b[j];
            #pragma unroll
            for (int k = 0; k < 10; k++)
                s += features[b * 10 + k] * fc0_W[j * 10 + k];
            h0[j] = (s >= 0.f) ? s : a0 * s;
        }
        #pragma unroll
        for (int e = 0; e < 8; e++) {
            float s = fc1_b[e];
            #pragma unroll
            for (int j = 0; j < 16; j++)
                s += h0[j] * fc1_W[e * 16 + j];
            cs[tid * 12 + e] = (s >= 0.f) ? s : a1 * s;
        }
        cs[tid * 12 + 8] = 1.f;
    }
    __syncthreads();

    float acc[16];                                 // [mh*8 + ni*4 + r]
    #pragma unroll
    for (int r = 0; r < 16; r++) acc[r] = 0.f;

    // ---- mainloop: e outer (z-fold), ii inner; prefetch c+2 ----
    #pragma unroll
    for (int e = 0; e < 9; e++) {
        float z[16];
        #pragma unroll
        for (int r = 0; r < 16; r++) z[r] = 0.f;

        #pragma unroll
        for (int ii = 0; ii < 4; ii++) {
            const int c = e * 4 + ii;
            if (c + 2 < NCH) LOADB((c + 2) % 3, c + 2)

            // A-frags: 8 x LDS.128 (ki packed in float4)
            float4 A[2][4];                        // [mh][a0..a3]
            #pragma unroll
            for (int mh = 0; mh < 2; mh++) {
                const float4* base = xt + (m0 + mh * 16 + g) * 36 + ii * 8;
                A[mh][0] = base[q];
                A[mh][1] = base[8 * 36 + q];
                A[mh][2] = base[q + 4];
                A[mh][3] = base[8 * 36 + q + 4];
            }

            #pragma unroll
            for (int ki = 0; ki < 4; ki++) {
                #pragma unroll
                for (int ni = 0; ni < 2; ni++) {
                    const float4 f = br[c % 3][ni * 2 + (ki >> 1)];
                    const uint32_t bb0 = (ki & 1) ? __float_as_uint(f.z) : __float_as_uint(f.x);
                    const uint32_t bb1 = (ki & 1) ? __float_as_uint(f.w) : __float_as_uint(f.y);
                    #pragma unroll
                    for (int mh = 0; mh < 2; mh++) {
                        const float* av0 = (const float*)&A[mh][0];
                        const float* av1 = (const float*)&A[mh][1];
                        const float* av2 = (const float*)&A[mh][2];
                        const float* av3 = (const float*)&A[mh][3];
                        mma_tf32(z[mh * 8 + ni * 4 + 0], z[mh * 8 + ni * 4 + 1],
                                 z[mh * 8 + ni * 4 + 2], z[mh * 8 + ni * 4 + 3],
                                 __float_as_uint(av0[ki]), __float_as_uint(av1[ki]),
                                 __float_as_uint(av2[ki]), __float_as_uint(av3[ki]),
                                 bb0, bb1);
                    }
                }
            }
        }

        // fold: d0,d1 live on row (..+g); d2,d3 on row (..+g+8)
        #pragma unroll
        for (int mh = 0; mh < 2; mh++) {
            const float cbl = cs[(m0 + mh * 16 + g) * 12 + e];
            const float cbh = cs[(m0 + mh * 16 + g + 8) * 12 + e];
            #pragma unroll
            for (int ni = 0; ni < 2; ni++) {
                acc[mh * 8 + ni * 4 + 0] += cbl * z[mh * 8 + ni * 4 + 0];
                acc[mh * 8 + ni * 4 + 1] += cbl * z[mh * 8 + ni * 4 + 1];
                acc[mh * 8 + ni * 4 + 2] += cbh * z[mh * 8 + ni * 4 + 2];
                acc[mh * 8 + ni * 4 + 3] += cbh * z[mh * 8 + ni * 4 + 3];
            }
        }
    }

    // ---- epilogue: add bias sum_e c[row,e]*WB[e][col], then store ----
    const int colbase = nh * 64 + wc * 16;
    #pragma unroll
    for (int mh = 0; mh < 2; mh++) {
        const int rl = m0 + mh * 16 + g;           // local rows rl, rl+8
        #pragma unroll
        for (int ni = 0; ni < 2; ni++) {
            const int col = colbase + ni * 8 + 2 * q;
            float s0 = acc[mh * 8 + ni * 4 + 0], s1 = acc[mh * 8 + ni * 4 + 1];
            float s2 = acc[mh * 8 + ni * 4 + 2], s3 = acc[mh * 8 + ni * 4 + 3];
            #pragma unroll
            for (int e = 0; e < 9; e++) {
                const float c0 = cs[rl * 12 + e];
                const float c1 = cs[(rl + 8) * 12 + e];
                const float w0 = wb[e * 128 + col];
                const float w1 = wb[e * 128 + col + 1];
                s0 += c0 * w0; s1 += c0 * w1;
                s2 += c1 * w0; s3 += c1 * w1;
            }
            *(float2*)(out + (size_t)(b0row + rl)     * OUT_F + col) = make_float2(s0, s1);
            *(float2*)(out + (size_t)(b0row + rl + 8) * OUT_F + col) = make_float2(s2, s3);
        }
    }
}

// ---------------------------------------------------------------------------
extern "C" void kernel_launch(void* const* d_in, const int* in_sizes, int n_in,
                              void* d_out, int out_size) {
    const float* x        = (const float*)d_in[0];
    const float* features = (const float*)d_in[1];
    const float* fc0_W    = (const float*)d_in[2];
    const float* fc0_b    = (const float*)d_in[3];
    const float* a0       = (const float*)d_in[4];
    const float* fc1_W    = (const float*)d_in[5];
    const float* fc1_b    = (const float*)d_in[6];
    const float* a1       = (const float*)d_in[7];
    const float* gen_W    = (const float*)d_in[8];
    const float* gen_b    = (const float*)d_in[9];
    float* out = (float*)d_out;

    b_kernel<<<NCH * 16, 256>>>(gen_W, gen_b);
    gemm_kernel<<<128, 256>>>(x, features, fc0_W, fc0_b, a0,
                              fc1_W, fc1_b, a1, out);
}

// round 15
// speedup vs baseline: 1.0122x; 1.0122x over previous
#include <cuda_runtime.h>
#include <cstdint>

#define BATCH 4096
#define IN_F 128
#define OUT_F 128
#define NW (IN_F * OUT_F)
#define NCH 36               // 36 x-chunks (9e x 4 i-groups); bias via epilogue

// B operand, fragment-major, warp-slice-contiguous (tf32-rounded):
// f4 index ((c*8 + s)*4 + j)*32 + lane, s = nh*4+wc, j = ni*2+p, word w=0..3
//   o = (s>>2)*64 + (s&3)*16 + (j>>1)*8 + (lane>>2)
//   k = c*32 + (j&1)*16 + (w>>1)*8 + (w&1)*4 + (lane&3)
__device__ float d_Btf[NCH * 8 * 4 * 32 * 4];
// Bias generator WB[e][o] (fp32)
__device__ float d_WB[9 * 128];

// ---------------------------------------------------------------------------
// Helpers (baseline PTX only — toolchain compiles via compute_103, no tcgen05)
// ---------------------------------------------------------------------------
__device__ __forceinline__ uint32_t smem_u32(const void* p) {
    uint32_t a;
    asm("{ .reg .u64 t; cvta.to.shared.u64 t, %1; cvt.u32.u64 %0, t; }" : "=r"(a) : "l"(p));
    return a;
}
__device__ __forceinline__ float tf32r(float x) {
    uint32_t r;
    asm("cvt.rn.tf32.f32 %0, %1;" : "=r"(r) : "f"(x));
    return __uint_as_float(r);
}
__device__ __forceinline__ void cpca16(uint32_t s, const void* g) {
    asm volatile("cp.async.ca.shared.global [%0], [%1], 16;" :: "r"(s), "l"(g));
}
#define CP_COMMIT() asm volatile("cp.async.commit_group;" ::: "memory")
#define CP_WAIT2()  asm volatile("cp.async.wait_group 2;" ::: "memory")

__device__ __forceinline__ void mma_tf32(float& d0, float& d1, float& d2, float& d3,
                                         uint32_t a0, uint32_t a1, uint32_t a2, uint32_t a3,
                                         uint32_t b0, uint32_t b1) {
    asm volatile(
        "mma.sync.aligned.m16n8k8.row.col.f32.tf32.tf32.f32 "
        "{%0,%1,%2,%3}, {%4,%5,%6,%7}, {%8,%9}, {%0,%1,%2,%3};"
        : "+f"(d0), "+f"(d1), "+f"(d2), "+f"(d3)
        : "r"(a0), "r"(a1), "r"(a2), "r"(a3), "r"(b0), "r"(b1));
}

// ---------------------------------------------------------------------------
// Prep: build d_Btf (new layout) and d_WB. 576 blocks x 256 thr, coalesced.
// ---------------------------------------------------------------------------
__global__ __launch_bounds__(256) void b_kernel(const float* __restrict__ gen_W,
                                                const float* __restrict__ gen_b) {
    const int idx = blockIdx.x * 256 + threadIdx.x;   // < 36*8*4*32*4 = 147456
    const int w    = idx & 3;
    const int lane = (idx >> 2) & 31;
    const int j    = (idx >> 7) & 3;
    const int s    = (idx >> 9) & 7;
    const int c    = idx >> 12;
    const int o = (s >> 2) * 64 + (s & 3) * 16 + (j >> 1) * 8 + (lane >> 2);
    const int k = c * 32 + (j & 1) * 16 + (w >> 1) * 8 + (w & 1) * 4 + (lane & 3);
    const int e = k >> 7, i = k & 127, p8 = o * 128 + i;
    const float v = (e < 8) ? gen_W[p8 * 8 + e] : gen_b[p8];
    d_Btf[idx] = tf32r(v);

    if (idx < 9 * 128) {
        const int eb = idx >> 7, ob = idx & 127;
        d_WB[idx] = (eb < 8) ? gen_W[(NW + ob) * 8 + eb] : gen_b[NW + ob];
    }
}

// ---------------------------------------------------------------------------
// Fused GEMM: CTA 256 thr, tile M=64 x N=64, grid 128 = (m-tile) x (n-half).
// Warp tile M32 x N16: wr=wid&1, wc=wid>>1. Full K per warp.
// B: warp-private cp.async ring, depth 4 (2KB/chunk/warp). Each lane async-
// copies exactly its own fragment bytes -> per-thread wait_group is the only
// ordering needed; NO barriers in the mainloop.
// A: fragment-major xt in smem (tf32 pre-rounded), 8x LDS.128 per chunk.
// e-outer z-fold; bias via fp32 FFMA epilogue.
// ---------------------------------------------------------------------------
// dynamic smem layout (f4 units):
//   xt:   [0, 2304)            64 rows x 36 f4    (36864 B)
//   ring: [2304, 2304+4096)    8 warps x 4 slots x 4 j x 32 lanes (65536 B)
//   cs:   floats after ring    64 x 12            (3072 B)
//   wb:   floats after cs      9 x 128            (4608 B)
#define XT_F4   0
#define RING_F4 2304
#define CS_FL   ((RING_F4 + 4096) * 4)            // float index
#define WB_FL   (CS_FL + 64 * 12)
#define SMEM_BYTES ((WB_FL + 9 * 128) * 4)        // 110080

__global__ __launch_bounds__(256, 1) void gemm_kernel(
    const float* __restrict__ x,
    const float* __restrict__ features,
    const float* __restrict__ fc0_W, const float* __restrict__ fc0_b,
    const float* __restrict__ a0p,
    const float* __restrict__ fc1_W, const float* __restrict__ fc1_b,
    const float* __restrict__ a1p,
    float* __restrict__ out)
{
    extern __shared__ __align__(16) float4 smf4[];
    float4* xt = smf4 + XT_F4;
    float*  smf = (float*)smf4;
    float*  cs = smf + CS_FL;
    float*  wb = smf + WB_FL;

    const int tid = threadIdx.x, wid = tid >> 5, lid = tid & 31;
    const int mt = blockIdx.x >> 1, nh = blockIdx.x & 1;
    const int b0row = mt * 64;
    const int wr = wid & 1, wc = wid >> 1;         // 2 m-warps x 4 n-warps
    const int m0 = wr * 32;
    const int g = lid >> 2, q = lid & 3;

    // ring addressing (bytes) and gmem source base for this warp's B slice
    const uint32_t ring_b = smem_u32(smf4) + RING_F4 * 16 + wid * 4 * 4 * 32 * 16;
    const float4* bsrc = (const float4*)d_Btf;     // + ((c*8+s)*4+j)*32 + lid
    const int sidx = nh * 4 + wc;

    // STAGE chunk c into slot: 4 cp.async.ca of 16B (lane loads its own frag)
    #define STAGE(slot, c)                                                    \
        _Pragma("unroll")                                                     \
        for (int j = 0; j < 4; j++)                                           \
            cpca16(ring_b + ((slot) * 4 + j) * 512 + lid * 16,                \
                   bsrc + (((c) * 8 + sidx) * 4 + j) * 32 + lid);

    STAGE(0, 0) CP_COMMIT();
    STAGE(1, 1) CP_COMMIT();
    STAGE(2, 2) CP_COMMIT();

    // ---- x tile, fragment-major, tf32-rounded: xt[r*36+w] w=ii*8+q' ----
    #pragma unroll
    for (int jj = 0; jj < 8; jj++) {
        const int sI = tid + 256 * jj;
        const int r = sI >> 5, ww = sI & 31;
        const float* xr = x + (size_t)(b0row + r) * IN_F + (ww >> 3) * 32 + (ww & 7);
        float4 v;
        v.x = tf32r(xr[0]);  v.y = tf32r(xr[8]);
        v.z = tf32r(xr[16]); v.w = tf32r(xr[24]);
        xt[r * 36 + ww] = v;
    }

    // ---- WB -> smem ----
    for (int j = tid; j < 9 * 128; j += 256) wb[j] = d_WB[j];

    // ---- tiny MLP: threads 0-63 -> cs[row*12+e] ----
    if (tid < 64) {
        const int b = b0row + tid;
        const float a0 = a0p[0], a1 = a1p[0];
        float h0[16];
        #pragma unroll
        for (int j = 0; j < 16; j++) {
            float s = fc0_b[j];
            #pragma unroll
            for (int k = 0; k < 10; k++)
                s += features[b * 10 + k] * fc0_W[j * 10 + k];
            h0[j] = (s >= 0.f) ? s : a0 * s;
        }
        #pragma unroll
        for (int e = 0; e < 8; e++) {
            float s = fc1_b[e];
            #pragma unroll
            for (int j = 0; j < 16; j++)
                s += h0[j] * fc1_W[e * 16 + j];
            cs[tid * 12 + e] = (s >= 0.f) ? s : a1 * s;
        }
        cs[tid * 12 + 8] = 1.f;
    }
    __syncthreads();                               // publishes xt/cs/wb only

    const float4* ringr = (const float4*)(smf4 + RING_F4) + wid * 4 * 4 * 32;

    float acc[16];
    #pragma unroll
    for (int r = 0; r < 16; r++) acc[r] = 0.f;

    // ---- mainloop: e outer (fold), ii inner. wait_group 2 => chunk c ready.
    #pragma unroll
    for (int e = 0; e < 9; e++) {
        float z[16];
        #pragma unroll
        for (int r = 0; r < 16; r++) z[r] = 0.f;

        #pragma unroll
        for (int ii = 0; ii < 4; ii++) {
            const int c = e * 4 + ii;
            CP_WAIT2();                            // own-lane data: no syncwarp

            // B frags: 4 x LDS.128 (conflict-free: bank = 4*lane_in_phase)
            float4 B[4];
            #pragma unroll
            for (int j = 0; j < 4; j++)
                B[j] = ringr[((c & 3) * 4 + j) * 32 + lid];

            // A frags: 8 x LDS.128 from fragment-major xt
            float4 A[2][4];
            #pragma unroll
            for (int mh = 0; mh < 2; mh++) {
                const float4* base = xt + (m0 + mh * 16 + g) * 36 + ii * 8;
                A[mh][0] = base[q];
                A[mh][1] = base[8 * 36 + q];
                A[mh][2] = base[q + 4];
                A[mh][3] = base[8 * 36 + q + 4];
            }

            // refill slot (c+3)&3 with chunk c+3 (consumed at c-1 by this warp)
            if (c + 3 < NCH) { STAGE((c + 3) & 3, c + 3) }
            CP_COMMIT();                           // uniform group count

            #pragma unroll
            for (int ki = 0; ki < 4; ki++) {
                #pragma unroll
                for (int ni = 0; ni < 2; ni++) {
                    const float4 f = B[ni * 2 + (ki >> 1)];
                    const uint32_t bb0 = (ki & 1) ? __float_as_uint(f.z) : __float_as_uint(f.x);
                    const uint32_t bb1 = (ki & 1) ? __float_as_uint(f.w) : __float_as_uint(f.y);
                    #pragma unroll
                    for (int mh = 0; mh < 2; mh++) {
                        const float* a0v = (const float*)&A[mh][0];
                        const float* a1v = (const float*)&A[mh][1];
                        const float* a2v = (const float*)&A[mh][2];
                        const float* a3v = (const float*)&A[mh][3];
                        mma_tf32(z[mh * 8 + ni * 4 + 0], z[mh * 8 + ni * 4 + 1],
                                 z[mh * 8 + ni * 4 + 2], z[mh * 8 + ni * 4 + 3],
                                 __float_as_uint(a0v[ki]), __float_as_uint(a1v[ki]),
                                 __float_as_uint(a2v[ki]), __float_as_uint(a3v[ki]),
                                 bb0, bb1);
                    }
                }
            }
        }

        #pragma unroll
        for (int mh = 0; mh < 2; mh++) {
            const float cbl = cs[(m0 + mh * 16 + g) * 12 + e];
            const float cbh = cs[(m0 + mh * 16 + g + 8) * 12 + e];
            #pragma unroll
            for (int ni = 0; ni < 2; ni++) {
                acc[mh * 8 + ni * 4 + 0] += cbl * z[mh * 8 + ni * 4 + 0];
                acc[mh * 8 + ni * 4 + 1] += cbl * z[mh * 8 + ni * 4 + 1];
                acc[mh * 8 + ni * 4 + 2] += cbh * z[mh * 8 + ni * 4 + 2];
                acc[mh * 8 + ni * 4 + 3] += cbh * z[mh * 8 + ni * 4 + 3];
            }
        }
    }

    // ---- epilogue: bias sum_e c[row,e]*WB[e][col], then coalesced stores ----
    const int colbase = nh * 64 + wc * 16;
    #pragma unroll
    for (int mh = 0; mh < 2; mh++) {
        const int rl = m0 + mh * 16 + g;
        #pragma unroll
        for (int ni = 0; ni < 2; ni++) {
            const int col = colbase + ni * 8 + 2 * q;
            float s0 = acc[mh * 8 + ni * 4 + 0], s1 = acc[mh * 8 + ni * 4 + 1];
            float s2 = acc[mh * 8 + ni * 4 + 2], s3 = acc[mh * 8 + ni * 4 + 3];
            #pragma unroll
            for (int e = 0; e < 9; e++) {
                const float c0 = cs[rl * 12 + e];
                const float c1 = cs[(rl + 8) * 12 + e];
                const float w0 = wb[e * 128 + col];
                const float w1 = wb[e * 128 + col + 1];
                s0 += c0 * w0; s1 += c0 * w1;
                s2 += c1 * w0; s3 += c1 * w1;
            }
            *(float2*)(out + (size_t)(b0row + rl)     * OUT_F + col) = make_float2(s0, s1);
            *(float2*)(out + (size_t)(b0row + rl + 8) * OUT_F + col) = make_float2(s2, s3);
        }
    }
}

// ---------------------------------------------------------------------------
extern "C" void kernel_launch(void* const* d_in, const int* in_sizes, int n_in,
                              void* d_out, int out_size) {
    const float* x        = (const float*)d_in[0];
    const float* features = (const float*)d_in[1];
    const float* fc0_W    = (const float*)d_in[2];
    const float* fc0_b    = (const float*)d_in[3];
    const float* a0       = (const float*)d_in[4];
    const float* fc1_W    = (const float*)d_in[5];
    const float* fc1_b    = (const float*)d_in[6];
    const float* a1       = (const float*)d_in[7];
    const float* gen_W    = (const float*)d_in[8];
    const float* gen_b    = (const float*)d_in[9];
    float* out = (float*)d_out;

    b_kernel<<<576, 256>>>(gen_W, gen_b);

    cudaFuncSetAttribute(gemm_kernel,
                         cudaFuncAttributeMaxDynamicSharedMemorySize, SMEM_BYTES);
    gemm_kernel<<<128, 256, SMEM_BYTES>>>(x, features, fc0_W, fc0_b, a0,
                                          fc1_W, fc1_b, a1, out);
}